// round 14
// baseline (speedup 1.0000x reference)
#include <cuda_runtime.h>
#include <cuda_fp16.h>
#include <math.h>
#include <stdint.h>

#define BB 1536
#define SEQ 12

// ---------------- device scratch (no allocation) ------------------------------
__device__ float g_h[BB*128], g_c[BB*128];
__device__ float g_lp[BB*2];
__device__ float g_part[4*BB*512];                 // split-K partial sums
__device__ float g_hcon[BB*512];                   // summed hcon (+biasc), fp32
__device__ float g_M0[512], g_M1[512], g_biasc[512], g_biasg[512];
// fp16 hi/lo split operands: uint2{half2(hi), half2(lo)} per k-pair
__device__ uint2 g_Xg[BB*96];          // gates input split: [row][k2] (decin 0..31 | h 32..95)
__device__ uint2 g_Xm1[BB*576];        // mlp1 input split: hl 0..63 | pool 64..575
__device__ uint2 g_Ysp[BB*512];        // mlp2 input split (mlp1 output)
__device__ uint2 g_Wgsp[96*512];       // weights, [k2][n]
__device__ uint2 g_W1sp[64*512];
__device__ uint2 g_Wp2sp[256*1024];
__device__ uint2 g_Wm1sp[576*1024];
__device__ uint2 g_Wm2sp[512*128];

// ---------------- helpers ------------------------------------------------------
__device__ __forceinline__ uint32_t smem_u32(const void* p) {
    uint32_t a;
    asm("{ .reg .u64 t; cvta.to.shared.u64 t, %1; cvt.u32.u64 %0, t; }" : "=r"(a) : "l"(p));
    return a;
}
__device__ __forceinline__ uint2 pack_split(float v0, float v1) {
    __half h0 = __float2half_rn(v0);
    __half h1 = __float2half_rn(v1);
    __half l0 = __float2half_rn(v0 - __half2float(h0));
    __half l1 = __float2half_rn(v1 - __half2float(h1));
    __half2 hh = __halves2half2(h0, h1);
    __half2 ll = __halves2half2(l0, l1);
    uint2 r;
    r.x = *reinterpret_cast<unsigned*>(&hh);
    r.y = *reinterpret_cast<unsigned*>(&ll);
    return r;
}
__device__ __forceinline__ void hmma(float* c, unsigned a0, unsigned a1, unsigned a2,
                                     unsigned a3, unsigned b0, unsigned b1) {
    asm("mma.sync.aligned.m16n8k16.row.col.f32.f16.f16.f32 "
        "{%0,%1,%2,%3},{%4,%5,%6,%7},{%8,%9},{%0,%1,%2,%3};"
        : "+f"(c[0]), "+f"(c[1]), "+f"(c[2]), "+f"(c[3])
        : "r"(a0), "r"(a1), "r"(a2), "r"(a3), "r"(b0), "r"(b1));
}

// ---------------- fp16x3 MMA GEMM, cp.async double-buffered --------------------
// block 96x128, 8 warps (2x4), warp 48x32 (3x4 m16n8k16 tiles), stage BK=32.
// mode 3: bias+relu, split-packed store (uint2) for the next GEMM
// mode 4: raw partial store (split-K slice z at C + z*Mfull*ldc), no bias
// mode 5: fp32 store with bias, no relu (hcon)
__global__ __launch_bounds__(256)
void hgemm_kernel(const uint2* __restrict__ Asp, int Astride, int kLen,
                  const uint2* __restrict__ Bsp, int Nfull,
                  const float* __restrict__ bias,
                  void* __restrict__ Cout, int ldc, int mode) {
    extern __shared__ uint2 smbuf[];                 // As[2][16][100] | Bs[2][16][132]
    uint2* AsBuf = smbuf;
    uint2* BsBuf = smbuf + 3200;
    uint32_t sb = smem_u32(smbuf);

    int tid = threadIdx.x;
    int lane = tid & 31, wid = tid >> 5;
    int g = lane >> 2, tg = lane & 3;
    int warpM = wid >> 2, warpN = wid & 3;
    int n0 = blockIdx.x * 128, m0 = blockIdx.y * 96;
    int z = blockIdx.z;
    int kOff = z * kLen;
    int S = kLen >> 4;                               // stages of 16 k2 (= K 32)

    auto issue = [&](int buf, int k0g) {
        uint32_t abase = sb + (uint32_t)buf * 1600u * 8u;
        int e = tid;
        #pragma unroll
        for (int it = 0; it < 6; it++, e += 256) {
            int r = e >> 4, q = e & 15;
            const void* src = Asp + (size_t)(m0 + r) * Astride + k0g + q;
            uint32_t dst = abase + (uint32_t)(q * 100 + r) * 8u;
            asm volatile("cp.async.ca.shared.global [%0], [%1], 8;" :: "r"(dst), "l"(src));
        }
        uint32_t bbase = sb + (3200u + (uint32_t)buf * 2112u) * 8u;
        e = tid;
        #pragma unroll
        for (int it = 0; it < 8; it++, e += 256) {
            int q = e >> 7, n = e & 127;
            const void* src = Bsp + (size_t)(k0g + q) * Nfull + n0 + n;
            uint32_t dst = bbase + (uint32_t)(q * 132 + n) * 8u;
            asm volatile("cp.async.ca.shared.global [%0], [%1], 8;" :: "r"(dst), "l"(src));
        }
        asm volatile("cp.async.commit_group;");
    };

    float acc[3][4][4];
    #pragma unroll
    for (int mt = 0; mt < 3; mt++)
        #pragma unroll
        for (int nt = 0; nt < 4; nt++)
            #pragma unroll
            for (int q = 0; q < 4; q++) acc[mt][nt][q] = 0.f;

    issue(0, kOff);
    for (int s = 0; s < S; s++) {
        if (s + 1 < S) {
            issue((s + 1) & 1, kOff + ((s + 1) << 4));
            asm volatile("cp.async.wait_group 1;");
        } else {
            asm volatile("cp.async.wait_group 0;");
        }
        __syncthreads();
        const uint2* As = AsBuf + (s & 1) * 1600;
        const uint2* Bs = BsBuf + (s & 1) * 2112;
        #pragma unroll
        for (int ks = 0; ks < 2; ks++) {
            int kb = ks * 8;
            unsigned ahi[3][4], alo[3][4];
            #pragma unroll
            for (int mt = 0; mt < 3; mt++) {
                int rb = warpM * 48 + mt * 16;
                uint2 x0 = As[(kb + tg) * 100 + rb + g];
                uint2 x1 = As[(kb + tg) * 100 + rb + g + 8];
                uint2 x2 = As[(kb + tg + 4) * 100 + rb + g];
                uint2 x3 = As[(kb + tg + 4) * 100 + rb + g + 8];
                ahi[mt][0] = x0.x; ahi[mt][1] = x1.x; ahi[mt][2] = x2.x; ahi[mt][3] = x3.x;
                alo[mt][0] = x0.y; alo[mt][1] = x1.y; alo[mt][2] = x2.y; alo[mt][3] = x3.y;
            }
            unsigned bhi[4][2], blo[4][2];
            #pragma unroll
            for (int nt = 0; nt < 4; nt++) {
                int nb = warpN * 32 + nt * 8;
                uint2 y0 = Bs[(kb + tg) * 132 + nb + g];
                uint2 y1 = Bs[(kb + tg + 4) * 132 + nb + g];
                bhi[nt][0] = y0.x; bhi[nt][1] = y1.x;
                blo[nt][0] = y0.y; blo[nt][1] = y1.y;
            }
            #pragma unroll
            for (int mt = 0; mt < 3; mt++)
                #pragma unroll
                for (int nt = 0; nt < 4; nt++) {
                    hmma(acc[mt][nt], ahi[mt][0], ahi[mt][1], ahi[mt][2], ahi[mt][3],
                         bhi[nt][0], bhi[nt][1]);
                    hmma(acc[mt][nt], ahi[mt][0], ahi[mt][1], ahi[mt][2], ahi[mt][3],
                         blo[nt][0], blo[nt][1]);
                    hmma(acc[mt][nt], alo[mt][0], alo[mt][1], alo[mt][2], alo[mt][3],
                         bhi[nt][0], bhi[nt][1]);
                }
        }
        __syncthreads();
    }

    if (mode == 4) {
        float* C = (float*)Cout + (size_t)z * (size_t)(gridDim.y * 96) * ldc;
        #pragma unroll
        for (int mt = 0; mt < 3; mt++) {
            int r0 = m0 + warpM * 48 + mt * 16 + g;
            #pragma unroll
            for (int nt = 0; nt < 4; nt++) {
                int c0 = n0 + warpN * 32 + nt * 8 + 2 * tg;
                *(float2*)&C[(size_t)r0 * ldc + c0]       = make_float2(acc[mt][nt][0], acc[mt][nt][1]);
                *(float2*)&C[(size_t)(r0 + 8) * ldc + c0] = make_float2(acc[mt][nt][2], acc[mt][nt][3]);
            }
        }
    } else if (mode == 3) {
        uint2* Y = (uint2*)Cout;
        int K2o = ldc >> 1;
        #pragma unroll
        for (int mt = 0; mt < 3; mt++) {
            int r0 = m0 + warpM * 48 + mt * 16 + g;
            #pragma unroll
            for (int nt = 0; nt < 4; nt++) {
                int c0 = n0 + warpN * 32 + nt * 8 + 2 * tg;
                float b0v = bias[c0], b1v = bias[c0 + 1];
                float v0 = fmaxf(acc[mt][nt][0] + b0v, 0.f);
                float v1 = fmaxf(acc[mt][nt][1] + b1v, 0.f);
                float v2 = fmaxf(acc[mt][nt][2] + b0v, 0.f);
                float v3 = fmaxf(acc[mt][nt][3] + b1v, 0.f);
                Y[(size_t)r0 * K2o + (c0 >> 1)]       = pack_split(v0, v1);
                Y[(size_t)(r0 + 8) * K2o + (c0 >> 1)] = pack_split(v2, v3);
            }
        }
    } else {  // mode 5: fp32 + bias (hcon)
        float* C = (float*)Cout;
        #pragma unroll
        for (int mt = 0; mt < 3; mt++) {
            int r0 = m0 + warpM * 48 + mt * 16 + g;
            #pragma unroll
            for (int nt = 0; nt < 4; nt++) {
                int c0 = n0 + warpN * 32 + nt * 8 + 2 * tg;
                float b0v = bias[c0], b1v = bias[c0 + 1];
                *(float2*)&C[(size_t)r0 * ldc + c0] =
                    make_float2(acc[mt][nt][0] + b0v, acc[mt][nt][1] + b1v);
                *(float2*)&C[(size_t)(r0 + 8) * ldc + c0] =
                    make_float2(acc[mt][nt][2] + b0v, acc[mt][nt][3] + b1v);
            }
        }
    }
}

// ---------------- fused pool kernel: layer-1 build + GEMM + max over j ---------
// block 96x128 = (4 i's x 24 j's) x 128 n, K=512 (16 stages of 32).
// A built in smem per stage from hcon tile + rel dirs; B = pre-split Wp2.
__global__ __launch_bounds__(256)
void pool_kernel(const uint2* __restrict__ Bsp, const float* __restrict__ bias,
                 uint2* __restrict__ Cout) {
    extern __shared__ char sm[];
    uint2*  AsBuf = (uint2*)sm;                       // 2*16*100  @0     (25600B)
    uint2*  BsBuf = (uint2*)(sm + 25600);             // 2*16*132         (33792B)
    float*  hsBuf = (float*)(sm + 59392);             // 2*24*36 floats   (6912B)
    float4* Ms4s  = (float4*)(sm + 66304);            // 256              (4096B)
    float*  ras   = (float*)(sm + 70400);             // 96
    float*  rbs   = (float*)(sm + 70784);             // 96
    int*    red   = (int*)(sm + 71168);               // 512              (2048B)
    uint32_t sb = smem_u32(sm);

    int tid = threadIdx.x;
    int lane = tid & 31, wid = tid >> 5;
    int g = lane >> 2, tg = lane & 3;
    int warpM = wid >> 2, warpN = wid & 3;
    int n0 = blockIdx.x * 128, m0 = blockIdx.y * 96;
    int grp = m0 / 576;
    int jb = grp * 24;

    if (tid < 96) {
        int i0 = (m0 % 576) / 24;
        int i = i0 + tid / 24, j = tid % 24;
        float pix = g_lp[(jb + i)*2 + 0], piy = g_lp[(jb + i)*2 + 1];
        float pjx = g_lp[(jb + j)*2 + 0], pjy = g_lp[(jb + j)*2 + 1];
        float dx = pjx - pix, dy = pjy - piy;
        float inv = 1.f / fmaxf(sqrtf(dx*dx + dy*dy), 1e-12f);
        ras[tid] = dx * inv; rbs[tid] = dy * inv;
    }
    Ms4s[tid] = make_float4(g_M0[2*tid], g_M1[2*tid], g_M0[2*tid+1], g_M1[2*tid+1]);
    for (int l = tid; l < 512; l += 256) red[l] = 0;

    auto issue = [&](int buf, int s) {
        uint32_t bbase = sb + 25600u + (uint32_t)buf * 2112u * 8u;
        int k0g = s << 4;
        int e = tid;
        #pragma unroll
        for (int it = 0; it < 8; it++, e += 256) {
            int q = e >> 7, n = e & 127;
            const void* src = Bsp + (size_t)(k0g + q) * 1024 + n0 + n;
            uint32_t dst = bbase + (uint32_t)(q * 132 + n) * 8u;
            asm volatile("cp.async.ca.shared.global [%0], [%1], 8;" :: "r"(dst), "l"(src));
        }
        if (tid < 192) {
            int j = tid >> 3, c = tid & 7;
            const void* src = &g_hcon[(size_t)(jb + j) * 512 + (s << 5) + c * 4];
            uint32_t dst = sb + 59392u + (uint32_t)buf * 3456u + (uint32_t)(j * 144 + c * 16);
            asm volatile("cp.async.ca.shared.global [%0], [%1], 16;" :: "r"(dst), "l"(src));
        }
        asm volatile("cp.async.commit_group;");
    };

    float acc[3][4][4];
    #pragma unroll
    for (int mt = 0; mt < 3; mt++)
        #pragma unroll
        for (int nt = 0; nt < 4; nt++)
            #pragma unroll
            for (int q = 0; q < 4; q++) acc[mt][nt][q] = 0.f;

    issue(0, 0);
    for (int s = 0; s < 16; s++) {
        asm volatile("cp.async.wait_group 0;");
        __syncthreads();                          // data(s) arrived; mma(s-1) retired
        if (s + 1 < 16) issue((s + 1) & 1, s + 1);
        int buf = s & 1;
        // build A(s): relu(ra*M0 + rb*M1 + hcon) then fp16 hi/lo split
        {
            const float* hs = hsBuf + buf * 864;
            uint2* As = AsBuf + buf * 1600;
            int e = tid;
            #pragma unroll
            for (int it = 0; it < 6; it++, e += 256) {
                int r = e % 96, q = e / 96;
                int j = r - (r / 24) * 24;
                float2 h2 = *(const float2*)&hs[j * 36 + 2 * q];
                float4 m = Ms4s[(s << 4) + q];
                float ra = ras[r], rb = rbs[r];
                float v0 = fmaxf(fmaf(ra, m.x, fmaf(rb, m.y, h2.x)), 0.f);
                float v1 = fmaxf(fmaf(ra, m.z, fmaf(rb, m.w, h2.y)), 0.f);
                As[q * 100 + r] = pack_split(v0, v1);
            }
        }
        __syncthreads();                          // A(s) ready
        const uint2* As = AsBuf + buf * 1600;
        const uint2* Bs = BsBuf + buf * 2112;
        #pragma unroll
        for (int ks = 0; ks < 2; ks++) {
            int kb = ks * 8;
            unsigned ahi[3][4], alo[3][4];
            #pragma unroll
            for (int mt = 0; mt < 3; mt++) {
                int rb2 = warpM * 48 + mt * 16;
                uint2 x0 = As[(kb + tg) * 100 + rb2 + g];
                uint2 x1 = As[(kb + tg) * 100 + rb2 + g + 8];
                uint2 x2 = As[(kb + tg + 4) * 100 + rb2 + g];
                uint2 x3 = As[(kb + tg + 4) * 100 + rb2 + g + 8];
                ahi[mt][0] = x0.x; ahi[mt][1] = x1.x; ahi[mt][2] = x2.x; ahi[mt][3] = x3.x;
                alo[mt][0] = x0.y; alo[mt][1] = x1.y; alo[mt][2] = x2.y; alo[mt][3] = x3.y;
            }
            unsigned bhi[4][2], blo[4][2];
            #pragma unroll
            for (int nt = 0; nt < 4; nt++) {
                int nb = warpN * 32 + nt * 8;
                uint2 y0 = Bs[(kb + tg) * 132 + nb + g];
                uint2 y1 = Bs[(kb + tg + 4) * 132 + nb + g];
                bhi[nt][0] = y0.x; bhi[nt][1] = y1.x;
                blo[nt][0] = y0.y; blo[nt][1] = y1.y;
            }
            #pragma unroll
            for (int mt = 0; mt < 3; mt++)
                #pragma unroll
                for (int nt = 0; nt < 4; nt++) {
                    hmma(acc[mt][nt], ahi[mt][0], ahi[mt][1], ahi[mt][2], ahi[mt][3],
                         bhi[nt][0], bhi[nt][1]);
                    hmma(acc[mt][nt], ahi[mt][0], ahi[mt][1], ahi[mt][2], ahi[mt][3],
                         blo[nt][0], blo[nt][1]);
                    hmma(acc[mt][nt], alo[mt][0], alo[mt][1], alo[mt][2], alo[mt][3],
                         bhi[nt][0], bhi[nt][1]);
                }
        }
        __syncthreads();
    }
    // epilogue: +bias, relu, max over 24-row buckets, split-packed to Xm1[64..]
    #pragma unroll
    for (int mt = 0; mt < 3; mt++) {
        int r = warpM * 48 + mt * 16 + g;
        int il0 = r / 24, il8 = (r + 8) / 24;
        #pragma unroll
        for (int nt = 0; nt < 4; nt++) {
            int n = warpN * 32 + nt * 8 + 2 * tg;
            float b0v = bias[n0 + n], b1v = bias[n0 + n + 1];
            atomicMax(&red[il0 * 128 + n],     __float_as_int(fmaxf(acc[mt][nt][0] + b0v, 0.f)));
            atomicMax(&red[il0 * 128 + n + 1], __float_as_int(fmaxf(acc[mt][nt][1] + b1v, 0.f)));
            atomicMax(&red[il8 * 128 + n],     __float_as_int(fmaxf(acc[mt][nt][2] + b0v, 0.f)));
            atomicMax(&red[il8 * 128 + n + 1], __float_as_int(fmaxf(acc[mt][nt][3] + b1v, 0.f)));
        }
    }
    __syncthreads();
    int bucket0 = blockIdx.y * 4;
    int il = tid >> 6, n2 = tid & 63;
    float v0 = __int_as_float(red[il * 128 + 2 * n2]);
    float v1 = __int_as_float(red[il * 128 + 2 * n2 + 1]);
    Cout[(size_t)(bucket0 + il) * 576 + 64 + (n0 >> 1) + n2] = pack_split(v0, v1);
}

// ---------------- precompute / weight splits ----------------------------------
__global__ void precompute_kernel(const float* __restrict__ Wp1,
                                  const float* __restrict__ Wp_emb,
                                  const float* __restrict__ bp_emb,
                                  const float* __restrict__ bp1,
                                  const float* __restrict__ bih,
                                  const float* __restrict__ bhh) {
    int idx = blockIdx.x * blockDim.x + threadIdx.x;
    if (idx < 512) {
        float m0 = 0.f, m1 = 0.f, bc = 0.f;
        for (int e = 0; e < 64; e++) {
            float w = Wp1[idx*192 + e];
            m0 += w * Wp_emb[e*2 + 0];
            m1 += w * Wp_emb[e*2 + 1];
            bc += w * bp_emb[e];
        }
        g_M0[idx] = m0; g_M1[idx] = m1;
        g_biasc[idx] = bp1[idx] + bc;
        g_biasg[idx] = bih[idx] + bhh[idx];
    }
}

__global__ void splitw_kernel(const float* __restrict__ Wih, const float* __restrict__ Whh,
                              const float* __restrict__ Wp1, const float* __restrict__ Wp2,
                              const float* __restrict__ Wm1, const float* __restrict__ Wm2) {
    int idx = blockIdx.x * blockDim.x + threadIdx.x;
    if (idx < 96*512) {
        int k2 = idx / 512, n = idx % 512, k = 2*k2;
        float v0 = (k < 64) ? Wih[n*64 + k]     : Whh[n*128 + (k - 64)];
        float v1 = (k+1 < 64) ? Wih[n*64 + k+1] : Whh[n*128 + (k+1 - 64)];
        g_Wgsp[idx] = pack_split(v0, v1);
    }
    if (idx < 64*512) {
        int k2 = idx / 512, n = idx % 512, k = 2*k2;
        g_W1sp[idx] = pack_split(Wp1[n*192 + 64 + k], Wp1[n*192 + 64 + k + 1]);
    }
    if (idx < 256*1024) {
        int k2 = idx >> 10, n = idx & 1023, k = 2*k2;
        g_Wp2sp[idx] = pack_split(Wp2[n*512 + k], Wp2[n*512 + k + 1]);
    }
    if (idx < 576*1024) {
        int k2 = idx >> 10, n = idx & 1023, k = 2*k2;
        g_Wm1sp[idx] = pack_split(Wm1[n*1152 + k], Wm1[n*1152 + k + 1]);
    }
    if (idx < 512*128) {
        int k2 = idx >> 7, n = idx & 127, k = 2*k2;
        g_Wm2sp[idx] = pack_split(Wm2[n*1024 + k], Wm2[n*1024 + k + 1]);
    }
}

__global__ void init_kernel(const float* __restrict__ h0, const float* __restrict__ c0,
                            const float* __restrict__ lp, const float* __restrict__ lpr,
                            const float* __restrict__ Wemb, const float* __restrict__ bemb) {
    int idx = blockIdx.x * blockDim.x + threadIdx.x;
    if (idx < BB*64) {
        int r = idx >> 6, u2 = idx & 63, u = 2*u2;
        float hv0 = h0[r*128 + u], hv1 = h0[r*128 + u + 1];
        *(float2*)&g_h[r*128 + u] = make_float2(hv0, hv1);
        *(float2*)&g_c[r*128 + u] = make_float2(c0[r*128 + u], c0[r*128 + u + 1]);
        g_Xg[r*96 + 32 + u2] = pack_split(hv0, hv1);
    }
    if (idx < BB*32) {
        int b = idx >> 5, t = idx & 31;
        int e0 = 2*t, e1 = 2*t + 1;
        float ra = lpr[b*2], rb = lpr[b*2 + 1];
        float v0 = ra*Wemb[e0*2] + rb*Wemb[e0*2+1] + bemb[e0];
        float v1 = ra*Wemb[e1*2] + rb*Wemb[e1*2+1] + bemb[e1];
        g_Xg[b*96 + t] = pack_split(v0, v1);
    }
    if (idx < BB*2) g_lp[idx] = lp[idx];
}

// fused: LSTM activations (from gate partials) + rel_pos + pos update + dec_in
__global__ void actpos_kernel(const float* __restrict__ Wpos, const float* __restrict__ bpos,
                              const float* __restrict__ Wemb, const float* __restrict__ bemb,
                              float* __restrict__ rels_out, int step) {
    int b = blockIdx.x;
    int t = threadIdx.x;      // 128
    __shared__ float hr[128];
    __shared__ float sr[2];
    {
        float gi = g_part[b*512 + t]       + g_part[BB*512 + b*512 + t]       + g_biasg[t];
        float gf = g_part[b*512 + t + 128] + g_part[BB*512 + b*512 + t + 128] + g_biasg[t + 128];
        float gg = g_part[b*512 + t + 256] + g_part[BB*512 + b*512 + t + 256] + g_biasg[t + 256];
        float go = g_part[b*512 + t + 384] + g_part[BB*512 + b*512 + t + 384] + g_biasg[t + 384];
        float si = 1.f / (1.f + __expf(-gi));
        float sf = 1.f / (1.f + __expf(-gf));
        float so = 1.f / (1.f + __expf(-go));
        float cc = sf * g_c[b*128 + t] + si * tanhf(gg);
        g_c[b*128 + t] = cc;
        hr[t] = so * tanhf(cc);
    }
    __syncthreads();
    if (t < 64) g_Xm1[b*576 + t] = pack_split(hr[2*t], hr[2*t + 1]);
    int w = t >> 5, lane = t & 31;
    if (w < 2) {
        float part = 0.f;
        for (int k = lane; k < 128; k += 32) part += hr[k] * Wpos[w*128 + k];
        #pragma unroll
        for (int off = 16; off; off >>= 1) part += __shfl_down_sync(0xffffffffu, part, off);
        if (lane == 0) sr[w] = part + bpos[w];
    }
    __syncthreads();
    float ra = sr[0], rb = sr[1];
    if (t < 32) {
        int e0 = 2*t, e1 = 2*t + 1;
        float v0 = ra*Wemb[e0*2] + rb*Wemb[e0*2+1] + bemb[e0];
        float v1 = ra*Wemb[e1*2] + rb*Wemb[e1*2+1] + bemb[e1];
        g_Xg[b*96 + t] = pack_split(v0, v1);
    }
    if (t == 0) {
        rels_out[(step*BB + b)*2 + 0] = ra;
        rels_out[(step*BB + b)*2 + 1] = rb;
        g_lp[b*2 + 0] += ra;
        g_lp[b*2 + 1] += rb;
    }
}

// h = relu(sum of mlp2 partials + bm2); writes h float + h-split for next gates
__global__ void finalize_kernel(const float* __restrict__ bm2) {
    int idx = blockIdx.x * blockDim.x + threadIdx.x;
    if (idx >= BB*64) return;
    int r = idx >> 6, u2 = idx & 63, u = 2*u2;
    float v[2];
    #pragma unroll
    for (int d = 0; d < 2; d++) {
        int uu = u + d;
        float s = bm2[uu];
        #pragma unroll
        for (int zz = 0; zz < 4; zz++) s += g_part[zz*BB*128 + r*128 + uu];
        v[d] = fmaxf(s, 0.f);
    }
    *(float2*)&g_h[r*128 + u] = make_float2(v[0], v[1]);
    g_Xg[r*96 + 32 + u2] = pack_split(v[0], v[1]);
}

__global__ void copyout_kernel(float* __restrict__ out) {
    int idx = blockIdx.x * blockDim.x + threadIdx.x;
    if (idx < BB*128) out[SEQ*BB*2 + idx] = g_h[idx];
}

// ---------------- launch -------------------------------------------------------
static void* sym_addr(const void* s) { void* p = nullptr; cudaGetSymbolAddress(&p, s); return p; }

extern "C" void kernel_launch(void* const* d_in, const int* in_sizes, int n_in,
                              void* d_out, int out_size) {
    const float* last_pos     = (const float*)d_in[0];
    const float* last_pos_rel = (const float*)d_in[1];
    const float* h0    = (const float*)d_in[2];
    const float* c0    = (const float*)d_in[3];
    const float* W_emb = (const float*)d_in[5];
    const float* b_emb = (const float*)d_in[6];
    const float* W_ih  = (const float*)d_in[7];
    const float* W_hh  = (const float*)d_in[8];
    const float* b_ih  = (const float*)d_in[9];
    const float* b_hh  = (const float*)d_in[10];
    const float* W_pos = (const float*)d_in[11];
    const float* b_pos = (const float*)d_in[12];
    const float* Wp_emb= (const float*)d_in[13];
    const float* bp_emb= (const float*)d_in[14];
    const float* Wp1   = (const float*)d_in[15];
    const float* bp1   = (const float*)d_in[16];
    const float* Wp2   = (const float*)d_in[17];
    const float* bp2   = (const float*)d_in[18];
    const float* Wm1   = (const float*)d_in[19];
    const float* bm1   = (const float*)d_in[20];
    const float* Wm2   = (const float*)d_in[21];
    const float* bm2   = (const float*)d_in[22];
    float* out = (float*)d_out;

    const int SMEMG = (3200 + 4224) * 8;        // 59392 for hgemm
    const int SMEMP = 73216;                    // pool kernel
    cudaFuncSetAttribute(hgemm_kernel, cudaFuncAttributeMaxDynamicSharedMemorySize, SMEMG);
    cudaFuncSetAttribute(pool_kernel,  cudaFuncAttributeMaxDynamicSharedMemorySize, SMEMP);

    float* p_part  = (float*)sym_addr(g_part);
    float* p_hcon  = (float*)sym_addr(g_hcon);
    float* p_biasc = (float*)sym_addr(g_biasc);
    uint2* p_Xg    = (uint2*)sym_addr(g_Xg);
    uint2* p_Xm1   = (uint2*)sym_addr(g_Xm1);
    uint2* p_Ysp   = (uint2*)sym_addr(g_Ysp);
    uint2* p_Wgsp  = (uint2*)sym_addr(g_Wgsp);
    uint2* p_W1sp  = (uint2*)sym_addr(g_W1sp);
    uint2* p_Wp2sp = (uint2*)sym_addr(g_Wp2sp);
    uint2* p_Wm1sp = (uint2*)sym_addr(g_Wm1sp);
    uint2* p_Wm2sp = (uint2*)sym_addr(g_Wm2sp);

    precompute_kernel<<<2, 256>>>(Wp1, Wp_emb, bp_emb, bp1, b_ih, b_hh);
    splitw_kernel<<<(576*1024 + 255)/256, 256>>>(W_ih, W_hh, Wp1, Wp2, Wm1, Wm2);
    init_kernel<<<(BB*64 + 255)/256, 256>>>(h0, c0, last_pos, last_pos_rel, W_emb, b_emb);

    for (int s = 0; s < SEQ; s++) {
        // gates: Xg(1536x96) @ Wg^T -> partials (split-K 2)
        hgemm_kernel<<<dim3(4, 16, 2), 256, SMEMG>>>(
            p_Xg, 96, 48, p_Wgsp, 512, nullptr, p_part, 512, 4);
        actpos_kernel<<<BB, 128>>>(W_pos, b_pos, W_emb, b_emb, out, s);
        // hcon: hl-split @ Wp1_h^T + biasc -> fp32 g_hcon (no split-K)
        hgemm_kernel<<<dim3(4, 16, 1), 256, SMEMG>>>(
            p_Xm1, 576, 64, p_W1sp, 512, p_biasc, p_hcon, 512, 5);
        // pool: fused layer-1 + [36864,512]@Wp2^T + bias + relu + max over j
        pool_kernel<<<dim3(8, 384), 256, SMEMP>>>(p_Wp2sp, bp2, p_Xm1);
        // mlp1: Xm1(1536x576) @ Wm1^T + bm1, relu -> split store Ysp
        hgemm_kernel<<<dim3(8, 16, 1), 256, SMEMG>>>(
            p_Xm1, 576, 576, p_Wm1sp, 1024, bm1, p_Ysp, 1024, 3);
        // mlp2: Ysp(1536x512) @ Wm2^T -> partials (split-K 4)
        hgemm_kernel<<<dim3(1, 16, 4), 256, SMEMG>>>(
            p_Ysp, 512, 128, p_Wm2sp, 128, nullptr, p_part, 128, 4);
        finalize_kernel<<<384, 256>>>(bm2);
    }
    copyout_kernel<<<(BB*128 + 255)/256, 256>>>(out);
}

// round 16
// speedup vs baseline: 1.2031x; 1.2031x over previous
#include <cuda_runtime.h>
#include <cuda_fp16.h>
#include <math.h>
#include <stdint.h>

#define BB 1536
#define SEQ 12

// ---------------- device scratch (no allocation) ------------------------------
__device__ float g_h[BB*128], g_c[BB*128];
__device__ float g_lp[BB*2];
__device__ float g_part[4*BB*512];                 // split-K partial sums
__device__ float g_hcon[BB*512];                   // hcon (+biasc), fp32
__device__ float g_M0[512], g_M1[512], g_biasc[512], g_biasg[512];
// fp16 hi/lo split operands: uint2{half2(hi), half2(lo)} per k-pair
__device__ uint2 g_Xg[BB*96];          // gates input split: [row][k2] (decin 0..31 | h 32..95)
__device__ uint2 g_Xm1[BB*576];        // mlp1 input split: hl 0..63 | pool 64..575
__device__ uint2 g_Ysp[BB*512];        // mlp2 input split (mlp1 output)
__device__ uint2 g_PAsp[36864*256];    // pool A split, [row][k2]
__device__ uint2 g_Wgsp[96*512];       // weights, [k2][n]
__device__ uint2 g_W1sp[64*512];
__device__ uint2 g_Wp2sp[256*1024];
__device__ uint2 g_Wm1sp[576*1024];
__device__ uint2 g_Wm2sp[512*128];

// ---------------- helpers ------------------------------------------------------
__device__ __forceinline__ uint32_t smem_u32(const void* p) {
    uint32_t a;
    asm("{ .reg .u64 t; cvta.to.shared.u64 t, %1; cvt.u32.u64 %0, t; }" : "=r"(a) : "l"(p));
    return a;
}
__device__ __forceinline__ uint2 pack_split(float v0, float v1) {
    __half h0 = __float2half_rn(v0);
    __half h1 = __float2half_rn(v1);
    __half l0 = __float2half_rn(v0 - __half2float(h0));
    __half l1 = __float2half_rn(v1 - __half2float(h1));
    __half2 hh = __halves2half2(h0, h1);
    __half2 ll = __halves2half2(l0, l1);
    uint2 r;
    r.x = *reinterpret_cast<unsigned*>(&hh);
    r.y = *reinterpret_cast<unsigned*>(&ll);
    return r;
}
__device__ __forceinline__ void hmma(float* c, unsigned a0, unsigned a1, unsigned a2,
                                     unsigned a3, unsigned b0, unsigned b1) {
    asm("mma.sync.aligned.m16n8k16.row.col.f32.f16.f16.f32 "
        "{%0,%1,%2,%3},{%4,%5,%6,%7},{%8,%9},{%0,%1,%2,%3};"
        : "+f"(c[0]), "+f"(c[1]), "+f"(c[2]), "+f"(c[3])
        : "r"(a0), "r"(a1), "r"(a2), "r"(a3), "r"(b0), "r"(b1));
}

// ---------------- fp16x3 MMA GEMM, cp.async double-buffered --------------------
// block 96x128, 8 warps (2x4), warp 48x32 (3x4 m16n8k16 tiles), stage BK=32.
// mode 2: pool (bias+relu+max over 24-row buckets, split-packed out to g_Xm1)
// mode 3: bias+relu, split-packed store (uint2) for the next GEMM
// mode 4: raw partial store (split-K slice z at C + z*Mfull*ldc), no bias
// mode 5: fp32 store with bias, no relu (hcon)
__global__ __launch_bounds__(256)
void hgemm_kernel(const uint2* __restrict__ Asp, int Astride, int kLen,
                  const uint2* __restrict__ Bsp, int Nfull,
                  const float* __restrict__ bias,
                  void* __restrict__ Cout, int ldc, int mode) {
    extern __shared__ uint2 smbuf[];                 // As[2][16][100] | Bs[2][16][132] | red
    uint2* AsBuf = smbuf;
    uint2* BsBuf = smbuf + 3200;
    int*   red   = (int*)(smbuf + 3200 + 4224);
    uint32_t sb = smem_u32(smbuf);

    int tid = threadIdx.x;
    int lane = tid & 31, wid = tid >> 5;
    int g = lane >> 2, tg = lane & 3;
    int warpM = wid >> 2, warpN = wid & 3;
    int n0 = blockIdx.x * 128, m0 = blockIdx.y * 96;
    int z = blockIdx.z;
    int kOff = z * kLen;
    int S = kLen >> 4;                               // stages of 16 k2 (= K 32)

    if (mode == 2) {
        for (int l = tid; l < 512; l += 256) red[l] = 0;
    }

    auto issue = [&](int buf, int k0g) {
        uint32_t abase = sb + (uint32_t)buf * 1600u * 8u;
        int e = tid;
        #pragma unroll
        for (int it = 0; it < 6; it++, e += 256) {
            int r = e >> 4, q = e & 15;
            const void* src = Asp + (size_t)(m0 + r) * Astride + k0g + q;
            uint32_t dst = abase + (uint32_t)(q * 100 + r) * 8u;
            asm volatile("cp.async.ca.shared.global [%0], [%1], 8;" :: "r"(dst), "l"(src));
        }
        uint32_t bbase = sb + (3200u + (uint32_t)buf * 2112u) * 8u;
        e = tid;
        #pragma unroll
        for (int it = 0; it < 8; it++, e += 256) {
            int q = e >> 7, n = e & 127;
            const void* src = Bsp + (size_t)(k0g + q) * Nfull + n0 + n;
            uint32_t dst = bbase + (uint32_t)(q * 132 + n) * 8u;
            asm volatile("cp.async.ca.shared.global [%0], [%1], 8;" :: "r"(dst), "l"(src));
        }
        asm volatile("cp.async.commit_group;");
    };

    float acc[3][4][4];
    #pragma unroll
    for (int mt = 0; mt < 3; mt++)
        #pragma unroll
        for (int nt = 0; nt < 4; nt++)
            #pragma unroll
            for (int q = 0; q < 4; q++) acc[mt][nt][q] = 0.f;

    issue(0, kOff);
    for (int s = 0; s < S; s++) {
        if (s + 1 < S) {
            issue((s + 1) & 1, kOff + ((s + 1) << 4));
            asm volatile("cp.async.wait_group 1;");
        } else {
            asm volatile("cp.async.wait_group 0;");
        }
        __syncthreads();
        const uint2* As = AsBuf + (s & 1) * 1600;
        const uint2* Bs = BsBuf + (s & 1) * 2112;
        #pragma unroll
        for (int ks = 0; ks < 2; ks++) {
            int kb = ks * 8;
            unsigned ahi[3][4], alo[3][4];
            #pragma unroll
            for (int mt = 0; mt < 3; mt++) {
                int rb = warpM * 48 + mt * 16;
                uint2 x0 = As[(kb + tg) * 100 + rb + g];
                uint2 x1 = As[(kb + tg) * 100 + rb + g + 8];
                uint2 x2 = As[(kb + tg + 4) * 100 + rb + g];
                uint2 x3 = As[(kb + tg + 4) * 100 + rb + g + 8];
                ahi[mt][0] = x0.x; ahi[mt][1] = x1.x; ahi[mt][2] = x2.x; ahi[mt][3] = x3.x;
                alo[mt][0] = x0.y; alo[mt][1] = x1.y; alo[mt][2] = x2.y; alo[mt][3] = x3.y;
            }
            unsigned bhi[4][2], blo[4][2];
            #pragma unroll
            for (int nt = 0; nt < 4; nt++) {
                int nb = warpN * 32 + nt * 8;
                uint2 y0 = Bs[(kb + tg) * 132 + nb + g];
                uint2 y1 = Bs[(kb + tg + 4) * 132 + nb + g];
                bhi[nt][0] = y0.x; bhi[nt][1] = y1.x;
                blo[nt][0] = y0.y; blo[nt][1] = y1.y;
            }
            #pragma unroll
            for (int mt = 0; mt < 3; mt++)
                #pragma unroll
                for (int nt = 0; nt < 4; nt++) {
                    hmma(acc[mt][nt], ahi[mt][0], ahi[mt][1], ahi[mt][2], ahi[mt][3],
                         bhi[nt][0], bhi[nt][1]);
                    hmma(acc[mt][nt], ahi[mt][0], ahi[mt][1], ahi[mt][2], ahi[mt][3],
                         blo[nt][0], blo[nt][1]);
                    hmma(acc[mt][nt], alo[mt][0], alo[mt][1], alo[mt][2], alo[mt][3],
                         bhi[nt][0], bhi[nt][1]);
                }
        }
        __syncthreads();
    }

    if (mode == 4) {
        float* C = (float*)Cout + (size_t)z * (size_t)(gridDim.y * 96) * ldc;
        #pragma unroll
        for (int mt = 0; mt < 3; mt++) {
            int r0 = m0 + warpM * 48 + mt * 16 + g;
            #pragma unroll
            for (int nt = 0; nt < 4; nt++) {
                int c0 = n0 + warpN * 32 + nt * 8 + 2 * tg;
                *(float2*)&C[(size_t)r0 * ldc + c0]       = make_float2(acc[mt][nt][0], acc[mt][nt][1]);
                *(float2*)&C[(size_t)(r0 + 8) * ldc + c0] = make_float2(acc[mt][nt][2], acc[mt][nt][3]);
            }
        }
    } else if (mode == 3) {
        uint2* Y = (uint2*)Cout;
        int K2o = ldc >> 1;
        #pragma unroll
        for (int mt = 0; mt < 3; mt++) {
            int r0 = m0 + warpM * 48 + mt * 16 + g;
            #pragma unroll
            for (int nt = 0; nt < 4; nt++) {
                int c0 = n0 + warpN * 32 + nt * 8 + 2 * tg;
                float b0v = bias[c0], b1v = bias[c0 + 1];
                float v0 = fmaxf(acc[mt][nt][0] + b0v, 0.f);
                float v1 = fmaxf(acc[mt][nt][1] + b1v, 0.f);
                float v2 = fmaxf(acc[mt][nt][2] + b0v, 0.f);
                float v3 = fmaxf(acc[mt][nt][3] + b1v, 0.f);
                Y[(size_t)r0 * K2o + (c0 >> 1)]       = pack_split(v0, v1);
                Y[(size_t)(r0 + 8) * K2o + (c0 >> 1)] = pack_split(v2, v3);
            }
        }
    } else if (mode == 5) {  // fp32 + bias (hcon)
        float* C = (float*)Cout;
        #pragma unroll
        for (int mt = 0; mt < 3; mt++) {
            int r0 = m0 + warpM * 48 + mt * 16 + g;
            #pragma unroll
            for (int nt = 0; nt < 4; nt++) {
                int c0 = n0 + warpN * 32 + nt * 8 + 2 * tg;
                float b0v = bias[c0], b1v = bias[c0 + 1];
                *(float2*)&C[(size_t)r0 * ldc + c0] =
                    make_float2(acc[mt][nt][0] + b0v, acc[mt][nt][1] + b1v);
                *(float2*)&C[(size_t)(r0 + 8) * ldc + c0] =
                    make_float2(acc[mt][nt][2] + b0v, acc[mt][nt][3] + b1v);
            }
        }
    } else {  // mode 2: pool
        #pragma unroll
        for (int mt = 0; mt < 3; mt++) {
            int r = warpM * 48 + mt * 16 + g;
            int il0 = r / 24, il8 = (r + 8) / 24;
            #pragma unroll
            for (int nt = 0; nt < 4; nt++) {
                int n = warpN * 32 + nt * 8 + 2 * tg;
                float b0v = bias[n0 + n], b1v = bias[n0 + n + 1];
                atomicMax(&red[il0 * 128 + n],     __float_as_int(fmaxf(acc[mt][nt][0] + b0v, 0.f)));
                atomicMax(&red[il0 * 128 + n + 1], __float_as_int(fmaxf(acc[mt][nt][1] + b1v, 0.f)));
                atomicMax(&red[il8 * 128 + n],     __float_as_int(fmaxf(acc[mt][nt][2] + b0v, 0.f)));
                atomicMax(&red[il8 * 128 + n + 1], __float_as_int(fmaxf(acc[mt][nt][3] + b1v, 0.f)));
            }
        }
        __syncthreads();
        int bucket0 = blockIdx.y * 4;
        int il = tid >> 6, n2 = tid & 63;
        float v0 = __int_as_float(red[il * 128 + 2 * n2]);
        float v1 = __int_as_float(red[il * 128 + 2 * n2 + 1]);
        ((uint2*)Cout)[(size_t)(bucket0 + il) * 576 + 64 + (n0 >> 1) + n2] = pack_split(v0, v1);
    }
}

// ---------------- precompute / weight splits ----------------------------------
__global__ void precompute_kernel(const float* __restrict__ Wp1,
                                  const float* __restrict__ Wp_emb,
                                  const float* __restrict__ bp_emb,
                                  const float* __restrict__ bp1,
                                  const float* __restrict__ bih,
                                  const float* __restrict__ bhh) {
    int idx = blockIdx.x * blockDim.x + threadIdx.x;
    if (idx < 512) {
        float m0 = 0.f, m1 = 0.f, bc = 0.f;
        for (int e = 0; e < 64; e++) {
            float w = Wp1[idx*192 + e];
            m0 += w * Wp_emb[e*2 + 0];
            m1 += w * Wp_emb[e*2 + 1];
            bc += w * bp_emb[e];
        }
        g_M0[idx] = m0; g_M1[idx] = m1;
        g_biasc[idx] = bp1[idx] + bc;
        g_biasg[idx] = bih[idx] + bhh[idx];
    }
}

__global__ void splitw_kernel(const float* __restrict__ Wih, const float* __restrict__ Whh,
                              const float* __restrict__ Wp1, const float* __restrict__ Wp2,
                              const float* __restrict__ Wm1, const float* __restrict__ Wm2) {
    int idx = blockIdx.x * blockDim.x + threadIdx.x;
    if (idx < 96*512) {
        int k2 = idx / 512, n = idx % 512, k = 2*k2;
        float v0 = (k < 64) ? Wih[n*64 + k]     : Whh[n*128 + (k - 64)];
        float v1 = (k+1 < 64) ? Wih[n*64 + k+1] : Whh[n*128 + (k+1 - 64)];
        g_Wgsp[idx] = pack_split(v0, v1);
    }
    if (idx < 64*512) {
        int k2 = idx / 512, n = idx % 512, k = 2*k2;
        g_W1sp[idx] = pack_split(Wp1[n*192 + 64 + k], Wp1[n*192 + 64 + k + 1]);
    }
    if (idx < 256*1024) {
        int k2 = idx >> 10, n = idx & 1023, k = 2*k2;
        g_Wp2sp[idx] = pack_split(Wp2[n*512 + k], Wp2[n*512 + k + 1]);
    }
    if (idx < 576*1024) {
        int k2 = idx >> 10, n = idx & 1023, k = 2*k2;
        g_Wm1sp[idx] = pack_split(Wm1[n*1152 + k], Wm1[n*1152 + k + 1]);
    }
    if (idx < 512*128) {
        int k2 = idx >> 7, n = idx & 127, k = 2*k2;
        g_Wm2sp[idx] = pack_split(Wm2[n*1024 + k], Wm2[n*1024 + k + 1]);
    }
}

__global__ void init_kernel(const float* __restrict__ h0, const float* __restrict__ c0,
                            const float* __restrict__ lp, const float* __restrict__ lpr,
                            const float* __restrict__ Wemb, const float* __restrict__ bemb) {
    int idx = blockIdx.x * blockDim.x + threadIdx.x;
    if (idx < BB*64) {
        int r = idx >> 6, u2 = idx & 63, u = 2*u2;
        float hv0 = h0[r*128 + u], hv1 = h0[r*128 + u + 1];
        *(float2*)&g_h[r*128 + u] = make_float2(hv0, hv1);
        *(float2*)&g_c[r*128 + u] = make_float2(c0[r*128 + u], c0[r*128 + u + 1]);
        g_Xg[r*96 + 32 + u2] = pack_split(hv0, hv1);
    }
    if (idx < BB*32) {
        int b = idx >> 5, t = idx & 31;
        int e0 = 2*t, e1 = 2*t + 1;
        float ra = lpr[b*2], rb = lpr[b*2 + 1];
        float v0 = ra*Wemb[e0*2] + rb*Wemb[e0*2+1] + bemb[e0];
        float v1 = ra*Wemb[e1*2] + rb*Wemb[e1*2+1] + bemb[e1];
        g_Xg[b*96 + t] = pack_split(v0, v1);
    }
    if (idx < BB*2) g_lp[idx] = lp[idx];
}

// fused: LSTM activations (from gate partials) + rel_pos + pos update + dec_in
__global__ void actpos_kernel(const float* __restrict__ Wpos, const float* __restrict__ bpos,
                              const float* __restrict__ Wemb, const float* __restrict__ bemb,
                              float* __restrict__ rels_out, int step) {
    int b = blockIdx.x;
    int t = threadIdx.x;      // 128
    __shared__ float hr[128];
    __shared__ float sr[2];
    {
        float gi = g_part[b*512 + t]       + g_part[BB*512 + b*512 + t]       + g_biasg[t];
        float gf = g_part[b*512 + t + 128] + g_part[BB*512 + b*512 + t + 128] + g_biasg[t + 128];
        float gg = g_part[b*512 + t + 256] + g_part[BB*512 + b*512 + t + 256] + g_biasg[t + 256];
        float go = g_part[b*512 + t + 384] + g_part[BB*512 + b*512 + t + 384] + g_biasg[t + 384];
        float si = 1.f / (1.f + __expf(-gi));
        float sf = 1.f / (1.f + __expf(-gf));
        float so = 1.f / (1.f + __expf(-go));
        float cc = sf * g_c[b*128 + t] + si * tanhf(gg);
        g_c[b*128 + t] = cc;
        hr[t] = so * tanhf(cc);
    }
    __syncthreads();
    if (t < 64) g_Xm1[b*576 + t] = pack_split(hr[2*t], hr[2*t + 1]);
    int w = t >> 5, lane = t & 31;
    if (w < 2) {
        float part = 0.f;
        for (int k = lane; k < 128; k += 32) part += hr[k] * Wpos[w*128 + k];
        #pragma unroll
        for (int off = 16; off; off >>= 1) part += __shfl_down_sync(0xffffffffu, part, off);
        if (lane == 0) sr[w] = part + bpos[w];
    }
    __syncthreads();
    float ra = sr[0], rb = sr[1];
    if (t < 32) {
        int e0 = 2*t, e1 = 2*t + 1;
        float v0 = ra*Wemb[e0*2] + rb*Wemb[e0*2+1] + bemb[e0];
        float v1 = ra*Wemb[e1*2] + rb*Wemb[e1*2+1] + bemb[e1];
        g_Xg[b*96 + t] = pack_split(v0, v1);
    }
    if (t == 0) {
        rels_out[(step*BB + b)*2 + 0] = ra;
        rels_out[(step*BB + b)*2 + 1] = rb;
        g_lp[b*2 + 0] += ra;
        g_lp[b*2 + 1] += rb;
    }
}

// pool A build + split from fp32 hcon (biasc already included): row = g*576+i*24+j
__global__ void asplit_kernel() {
    int row = blockIdx.x;
    int grp = row / 576;
    int rem = row - grp*576;
    int i = rem / 24, j = rem - (rem/24)*24;
    int t = threadIdx.x;
    float pix = g_lp[(grp*24 + i)*2 + 0];
    float piy = g_lp[(grp*24 + i)*2 + 1];
    float pjx = g_lp[(grp*24 + j)*2 + 0];
    float pjy = g_lp[(grp*24 + j)*2 + 1];
    float dx = pjx - pix, dy = pjy - piy;
    float inv = 1.f / fmaxf(sqrtf(dx*dx + dy*dy), 1e-12f);
    float ra = dx * inv, rb = dy * inv;
    int k = t * 4;
    const float4 hc = *(const float4*)&g_hcon[(size_t)(grp*24 + j)*512 + k];
    const float4 m0 = *(const float4*)&g_M0[k];
    const float4 m1 = *(const float4*)&g_M1[k];
    float v0 = fmaxf(fmaf(ra, m0.x, fmaf(rb, m1.x, hc.x)), 0.f);
    float v1 = fmaxf(fmaf(ra, m0.y, fmaf(rb, m1.y, hc.y)), 0.f);
    float v2 = fmaxf(fmaf(ra, m0.z, fmaf(rb, m1.z, hc.z)), 0.f);
    float v3 = fmaxf(fmaf(ra, m0.w, fmaf(rb, m1.w, hc.w)), 0.f);
    uint2 u0 = pack_split(v0, v1);
    uint2 u1 = pack_split(v2, v3);
    *(uint4*)&g_PAsp[(size_t)row*256 + 2*t] = make_uint4(u0.x, u0.y, u1.x, u1.y);
}

// h = relu(sum of mlp2 partials + bm2); writes h float + h-split for next gates
__global__ void finalize_kernel(const float* __restrict__ bm2) {
    int idx = blockIdx.x * blockDim.x + threadIdx.x;
    if (idx >= BB*64) return;
    int r = idx >> 6, u2 = idx & 63, u = 2*u2;
    float v[2];
    #pragma unroll
    for (int d = 0; d < 2; d++) {
        int uu = u + d;
        float s = bm2[uu];
        #pragma unroll
        for (int zz = 0; zz < 4; zz++) s += g_part[zz*BB*128 + r*128 + uu];
        v[d] = fmaxf(s, 0.f);
    }
    *(float2*)&g_h[r*128 + u] = make_float2(v[0], v[1]);
    g_Xg[r*96 + 32 + u2] = pack_split(v[0], v[1]);
}

__global__ void copyout_kernel(float* __restrict__ out) {
    int idx = blockIdx.x * blockDim.x + threadIdx.x;
    if (idx < BB*128) out[SEQ*BB*2 + idx] = g_h[idx];
}

// ---------------- launch -------------------------------------------------------
static void* sym_addr(const void* s) { void* p = nullptr; cudaGetSymbolAddress(&p, s); return p; }

extern "C" void kernel_launch(void* const* d_in, const int* in_sizes, int n_in,
                              void* d_out, int out_size) {
    const float* last_pos     = (const float*)d_in[0];
    const float* last_pos_rel = (const float*)d_in[1];
    const float* h0    = (const float*)d_in[2];
    const float* c0    = (const float*)d_in[3];
    const float* W_emb = (const float*)d_in[5];
    const float* b_emb = (const float*)d_in[6];
    const float* W_ih  = (const float*)d_in[7];
    const float* W_hh  = (const float*)d_in[8];
    const float* b_ih  = (const float*)d_in[9];
    const float* b_hh  = (const float*)d_in[10];
    const float* W_pos = (const float*)d_in[11];
    const float* b_pos = (const float*)d_in[12];
    const float* Wp_emb= (const float*)d_in[13];
    const float* bp_emb= (const float*)d_in[14];
    const float* Wp1   = (const float*)d_in[15];
    const float* bp1   = (const float*)d_in[16];
    const float* Wp2   = (const float*)d_in[17];
    const float* bp2   = (const float*)d_in[18];
    const float* Wm1   = (const float*)d_in[19];
    const float* bm1   = (const float*)d_in[20];
    const float* Wm2   = (const float*)d_in[21];
    const float* bm2   = (const float*)d_in[22];
    float* out = (float*)d_out;

    const int SMEMB = (3200 + 4224) * 8 + 4 * 128 * 4;   // 61440
    cudaFuncSetAttribute(hgemm_kernel, cudaFuncAttributeMaxDynamicSharedMemorySize, SMEMB);

    float* p_part  = (float*)sym_addr(g_part);
    float* p_hcon  = (float*)sym_addr(g_hcon);
    float* p_biasc = (float*)sym_addr(g_biasc);
    uint2* p_Xg    = (uint2*)sym_addr(g_Xg);
    uint2* p_Xm1   = (uint2*)sym_addr(g_Xm1);
    uint2* p_Ysp   = (uint2*)sym_addr(g_Ysp);
    uint2* p_PAsp  = (uint2*)sym_addr(g_PAsp);
    uint2* p_Wgsp  = (uint2*)sym_addr(g_Wgsp);
    uint2* p_W1sp  = (uint2*)sym_addr(g_W1sp);
    uint2* p_Wp2sp = (uint2*)sym_addr(g_Wp2sp);
    uint2* p_Wm1sp = (uint2*)sym_addr(g_Wm1sp);
    uint2* p_Wm2sp = (uint2*)sym_addr(g_Wm2sp);

    precompute_kernel<<<2, 256>>>(Wp1, Wp_emb, bp_emb, bp1, b_ih, b_hh);
    splitw_kernel<<<(576*1024 + 255)/256, 256>>>(W_ih, W_hh, Wp1, Wp2, Wm1, Wm2);
    init_kernel<<<(BB*64 + 255)/256, 256>>>(h0, c0, last_pos, last_pos_rel, W_emb, b_emb);

    for (int s = 0; s < SEQ; s++) {
        // gates: Xg(1536x96) @ Wg^T -> partials (split-K 2)
        hgemm_kernel<<<dim3(4, 16, 2), 256, SMEMB>>>(
            p_Xg, 96, 48, p_Wgsp, 512, nullptr, p_part, 512, 4);
        actpos_kernel<<<BB, 128>>>(W_pos, b_pos, W_emb, b_emb, out, s);
        // hcon: hl-split (Xm1 cols 0..63) @ Wp1_h^T + biasc -> fp32 g_hcon
        hgemm_kernel<<<dim3(4, 16, 1), 256, SMEMB>>>(
            p_Xm1, 576, 64, p_W1sp, 512, p_biasc, p_hcon, 512, 5);
        // pool A build + split (single fp32 hcon read)
        asplit_kernel<<<36864, 128>>>();
        // pool: [36864,512]@Wp2^T + bias + relu + max over j -> split into Xm1[64..575]
        hgemm_kernel<<<dim3(8, 384, 1), 256, SMEMB>>>(
            p_PAsp, 256, 256, p_Wp2sp, 1024, bp2, p_Xm1, 0, 2);
        // mlp1: Xm1(1536x576) @ Wm1^T + bm1, relu -> split store Ysp
        hgemm_kernel<<<dim3(8, 16, 1), 256, SMEMB>>>(
            p_Xm1, 576, 576, p_Wm1sp, 1024, bm1, p_Ysp, 1024, 3);
        // mlp2: Ysp(1536x512) @ Wm2^T -> partials (split-K 4)
        hgemm_kernel<<<dim3(1, 16, 4), 256, SMEMB>>>(
            p_Ysp, 512, 128, p_Wm2sp, 128, nullptr, p_part, 128, 4);
        finalize_kernel<<<384, 256>>>(bm2);
    }
    copyout_kernel<<<(BB*128 + 255)/256, 256>>>(out);
}